// round 2
// baseline (speedup 1.0000x reference)
#include <cuda_runtime.h>

#define NN 50000
#define EE 600000
#define DD 128
#define BB 128

// ---------------- scratch (device globals: allocation-free) ----------------
__device__ int   g_cnt[NN];          // in-degree incl. self-loop
__device__ int   g_rowoff[NN + 1];   // CSR row offsets (by dst)
__device__ int   g_fill[NN];         // atomic fill cursors
__device__ int   g_csr[EE + NN];     // src indices per dst
__device__ float g_z[NN * DD];
__device__ float g_hA[NN * DD];
__device__ float g_hB[NN * DD];
__device__ float g_as[NN * 4];
__device__ float g_ad[NN * 4];
__device__ float g_z0[DD];

// ---------------- CSR construction ----------------
__global__ void k_initcnt() {
    int i = blockIdx.x * blockDim.x + threadIdx.x;
    if (i < NN) g_cnt[i] = 1;  // self-loop
}

__global__ void k_count(const int* __restrict__ dst) {
    int e = blockIdx.x * blockDim.x + threadIdx.x;
    if (e < EE) atomicAdd(&g_cnt[dst[e]], 1);
}

__global__ void k_scan() {  // exclusive scan of g_cnt -> g_rowoff (single block, 1024 thr)
    __shared__ int wsum[32];
    int t = threadIdx.x, lane = t & 31, wid = t >> 5;
    int carry = 0;
    if (t == 0) g_rowoff[0] = 0;
    for (int base = 0; base < NN; base += 1024) {
        int i = base + t;
        int v = (i < NN) ? g_cnt[i] : 0;
        int x = v;
#pragma unroll
        for (int off = 1; off < 32; off <<= 1) {
            int y = __shfl_up_sync(0xffffffffu, x, off);
            if (lane >= off) x += y;
        }
        if (lane == 31) wsum[wid] = x;
        __syncthreads();
        if (wid == 0) {
            int s = wsum[lane];
#pragma unroll
            for (int off = 1; off < 32; off <<= 1) {
                int y = __shfl_up_sync(0xffffffffu, s, off);
                if (lane >= off) s += y;
            }
            wsum[lane] = s;
        }
        __syncthreads();
        int pref = wid ? wsum[wid - 1] : 0;
        if (i < NN) g_rowoff[i + 1] = carry + pref + x;
        int tot = wsum[31];
        __syncthreads();
        carry += tot;
    }
}

__global__ void k_prepfill() {  // self-loop goes in slot 0 of each segment
    int n = blockIdx.x * blockDim.x + threadIdx.x;
    if (n < NN) {
        int r = g_rowoff[n];
        g_csr[r] = n;
        g_fill[n] = r + 1;
    }
}

__global__ void k_fill(const int* __restrict__ src, const int* __restrict__ dst) {
    int e = blockIdx.x * blockDim.x + threadIdx.x;
    if (e < EE) {
        int d = dst[e];
        int p = atomicAdd(&g_fill[d], 1);
        g_csr[p] = src[e];
    }
}

__global__ void k_sortseg() {  // deterministic order within each dst segment
    int n = blockIdx.x * blockDim.x + threadIdx.x;
    if (n >= NN) return;
    int r0 = g_rowoff[n], r1 = g_rowoff[n + 1];
    for (int i = r0 + 1; i < r1; i++) {
        int v = g_csr[i];
        int j = i - 1;
        while (j >= r0 && g_csr[j] > v) { g_csr[j + 1] = g_csr[j]; j--; }
        g_csr[j + 1] = v;
    }
}

// ---------------- layer 0 closed form ----------------
// h0 rows are identical -> alpha uniform -> softmax = 1/deg -> out0 = z0*(1+deg)
__global__ void k_z0(const float* __restrict__ emb, const float* __restrict__ W0) {
    __shared__ float se[DD];
    int t = threadIdx.x;
    se[t] = emb[t];
    __syncthreads();
    float acc = 0.f;
    for (int k = 0; k < DD; k++) acc += se[k] * W0[k * DD + t];
    g_z0[t] = acc;
}

__global__ void k_h1(const float* __restrict__ emb) {
    int idx = blockIdx.x * blockDim.x + threadIdx.x;
    if (idx >= NN * DD) return;
    int n = idx >> 7, d = idx & 127;
    float o = g_z0[d] * (1.0f + (float)g_cnt[n]);
    o = o > 0.f ? o : expm1f(o);   // elu
    g_hA[idx] = o + emb[d];        // residual (h0 = emb row 0)
}

// ---------------- GEMM: z = h @ W  (M=50000, N=K=128) ----------------
__global__ void __launch_bounds__(256) k_gemm(int srcA, const float* __restrict__ W) {
    const float* __restrict__ A = srcA ? g_hA : g_hB;
    __shared__ float As[128][32];   // [m][k]
    __shared__ float Bs[32][128];   // [k][c]
    int tid = threadIdx.x;
    int tx = tid & 15, ty = tid >> 4;
    int row0 = blockIdx.x * 128;

    float acc[8][8];
#pragma unroll
    for (int i = 0; i < 8; i++)
#pragma unroll
        for (int j = 0; j < 8; j++) acc[i][j] = 0.f;

    for (int k0 = 0; k0 < 128; k0 += 32) {
        // load A tile (coalesced: 8 lanes per 128B row chunk)
#pragma unroll
        for (int i = 0; i < 4; i++) {
            int lin = tid + i * 256;   // 0..1023 float4 units
            int m = lin >> 3, kq = lin & 7;
            int row = row0 + m;
            float4 v = make_float4(0.f, 0.f, 0.f, 0.f);
            if (row < NN) v = *(const float4*)&A[row * 128 + k0 + kq * 4];
            *(float4*)&As[m][kq * 4] = v;
        }
        // load W tile (fully coalesced)
#pragma unroll
        for (int i = 0; i < 4; i++) {
            int lin = tid + i * 256;
            int k = lin >> 5, cq = lin & 31;
            *(float4*)&Bs[k][cq * 4] = *(const float4*)&W[(k0 + k) * 128 + cq * 4];
        }
        __syncthreads();
#pragma unroll
        for (int k = 0; k < 32; k++) {
            float a[8], b[8];
#pragma unroll
            for (int i = 0; i < 4; i++) {
                a[i]     = As[ty * 4 + i][k];
                a[4 + i] = As[64 + ty * 4 + i][k];
            }
            float4 bl = *(const float4*)&Bs[k][tx * 4];
            float4 bh = *(const float4*)&Bs[k][64 + tx * 4];
            b[0] = bl.x; b[1] = bl.y; b[2] = bl.z; b[3] = bl.w;
            b[4] = bh.x; b[5] = bh.y; b[6] = bh.z; b[7] = bh.w;
#pragma unroll
            for (int i = 0; i < 8; i++)
#pragma unroll
                for (int j = 0; j < 8; j++) acc[i][j] += a[i] * b[j];
        }
        __syncthreads();
    }
#pragma unroll
    for (int i = 0; i < 8; i++) {
        int row = row0 + (i < 4 ? ty * 4 + i : 64 + ty * 4 + (i - 4));
        if (row < NN) {
            *(float4*)&g_z[row * 128 + tx * 4] =
                make_float4(acc[i][0], acc[i][1], acc[i][2], acc[i][3]);
            *(float4*)&g_z[row * 128 + 64 + tx * 4] =
                make_float4(acc[i][4], acc[i][5], acc[i][6], acc[i][7]);
        }
    }
}

// ---------------- attention dot products: a_s[n,h], a_d[n,h] ----------------
__global__ void k_att(const float* __restrict__ attS, const float* __restrict__ attD) {
    int warp = (blockIdx.x * blockDim.x + threadIdx.x) >> 5;
    int lane = threadIdx.x & 31;
    if (warp >= NN) return;
    float4 z4 = *(const float4*)&g_z[warp * 128 + lane * 4];
    float4 s4 = *(const float4*)&attS[lane * 4];
    float4 d4 = *(const float4*)&attD[lane * 4];
    float ps = z4.x * s4.x + z4.y * s4.y + z4.z * s4.z + z4.w * s4.w;
    float pd = z4.x * d4.x + z4.y * d4.y + z4.z * d4.z + z4.w * d4.w;
#pragma unroll
    for (int off = 4; off; off >>= 1) {
        ps += __shfl_xor_sync(0xffffffffu, ps, off);
        pd += __shfl_xor_sync(0xffffffffu, pd, off);
    }
    if ((lane & 7) == 0) {
        int h = lane >> 3;
        g_as[warp * 4 + h] = ps;
        g_ad[warp * 4 + h] = pd;
    }
}

// ---------------- aggregation: softmax over in-edges + residual + elu ----------------
__global__ void __launch_bounds__(256) k_agg(int srcA) {
    const float* __restrict__ hin  = srcA ? g_hA : g_hB;
    float* __restrict__       hout = srcA ? g_hB : g_hA;
    int warp = (blockIdx.x * blockDim.x + threadIdx.x) >> 5;
    int lane = threadIdx.x & 31;
    if (warp >= NN) return;
    int n = warp;
    int r0 = g_rowoff[n], r1 = g_rowoff[n + 1];
    float4 ad4 = *(const float4*)&g_ad[n * 4];

    // pass 1: per-head max of leaky_relu(a_s[src]+a_d[n]) (lanes parallel over edges)
    float m0 = -1e30f, m1 = -1e30f, m2 = -1e30f, m3 = -1e30f;
    for (int i = r0 + lane; i < r1; i += 32) {
        int s = g_csr[i];
        float4 as4 = *(const float4*)&g_as[s * 4];
        float t0 = as4.x + ad4.x; t0 = t0 > 0.f ? t0 : 0.2f * t0; m0 = fmaxf(m0, t0);
        float t1 = as4.y + ad4.y; t1 = t1 > 0.f ? t1 : 0.2f * t1; m1 = fmaxf(m1, t1);
        float t2 = as4.z + ad4.z; t2 = t2 > 0.f ? t2 : 0.2f * t2; m2 = fmaxf(m2, t2);
        float t3 = as4.w + ad4.w; t3 = t3 > 0.f ? t3 : 0.2f * t3; m3 = fmaxf(m3, t3);
    }
#pragma unroll
    for (int off = 16; off; off >>= 1) {
        m0 = fmaxf(m0, __shfl_xor_sync(0xffffffffu, m0, off));
        m1 = fmaxf(m1, __shfl_xor_sync(0xffffffffu, m1, off));
        m2 = fmaxf(m2, __shfl_xor_sync(0xffffffffu, m2, off));
        m3 = fmaxf(m3, __shfl_xor_sync(0xffffffffu, m3, off));
    }
    int hh = lane >> 3;  // each lane owns 4 feature dims, all in one head
    float mh  = hh == 0 ? m0 : (hh == 1 ? m1 : (hh == 2 ? m2 : m3));
    float adh = hh == 0 ? ad4.x : (hh == 1 ? ad4.y : (hh == 2 ? ad4.z : ad4.w));

    // pass 2: den + weighted sum + plain sum (edges serial, dims lane-parallel)
    float den = 0.f;
    float w0 = 0.f, w1 = 0.f, w2 = 0.f, w3 = 0.f;
    float s0 = 0.f, s1 = 0.f, s2 = 0.f, s3 = 0.f;
    for (int c0 = r0; c0 < r1; c0 += 32) {
        int myi = c0 + lane;
        int mysrc = (myi < r1) ? g_csr[myi] : 0;
        int lim = min(32, r1 - c0);
        for (int j = 0; j < lim; j++) {
            int s = __shfl_sync(0xffffffffu, mysrc, j);
            float av = g_as[s * 4 + hh];
            float t = av + adh; t = t > 0.f ? t : 0.2f * t;
            float ex = __expf(t - mh);
            den += ex;
            float4 z4 = *(const float4*)&g_z[s * 128 + lane * 4];
            w0 += ex * z4.x; w1 += ex * z4.y; w2 += ex * z4.z; w3 += ex * z4.w;
            s0 += z4.x;      s1 += z4.y;      s2 += z4.z;      s3 += z4.w;
        }
    }
    float inv = 1.0f / den;
    float4 hv = *(const float4*)&hin[n * 128 + lane * 4];
    float o0 = w0 * inv + s0; o0 = o0 > 0.f ? o0 : expm1f(o0); o0 += hv.x;
    float o1 = w1 * inv + s1; o1 = o1 > 0.f ? o1 : expm1f(o1); o1 += hv.y;
    float o2 = w2 * inv + s2; o2 = o2 > 0.f ? o2 : expm1f(o2); o2 += hv.z;
    float o3 = w3 * inv + s3; o3 = o3 > 0.f ? o3 : expm1f(o3); o3 += hv.w;
    *(float4*)&hout[n * 128 + lane * 4] = make_float4(o0, o1, o2, o3);
}

// ---------------- readout: segment mean (ptr sorted) + MLP ----------------
__device__ __forceinline__ int lbound(const int* p, int n, int v) {
    int lo = 0, hi = n;
    while (lo < hi) {
        int mid = (lo + hi) >> 1;
        if (p[mid] < v) lo = mid + 1; else hi = mid;
    }
    return lo;
}

__global__ void k_readout(const int* __restrict__ ptr,
                          const float* __restrict__ w0, const float* __restrict__ b0,
                          const float* __restrict__ w1, const float* __restrict__ b1,
                          float* __restrict__ out) {
    const float* __restrict__ h = g_hA;  // final features live in g_hA
    int b = blockIdx.x;
    __shared__ int sb[2];
    int t = threadIdx.x;
    if (t == 0) sb[0] = lbound(ptr, NN, b);
    if (t == 1) sb[1] = lbound(ptr, NN, b + 1);
    __syncthreads();
    int lo = sb[0], hi = sb[1];

    __shared__ float red[256];
    int d = t & 127, half = t >> 7;
    float s = 0.f;
    for (int r = lo + half; r < hi; r += 2) s += h[r * 128 + d];
    red[t] = s;
    __syncthreads();

    __shared__ float g[128];
    if (t < 128) {
        float gv = red[t] + red[t + 128];
        int cnt = hi - lo; if (cnt < 1) cnt = 1;
        gv = gv / (float)cnt;
        g[t] = fmaxf(gv, 0.f);
    }
    __syncthreads();

    __shared__ float hid[64];
    if (t < 64) {
        float acc = b0[t];
        for (int k = 0; k < 128; k++) acc += g[k] * w0[k * 64 + t];
        hid[t] = fmaxf(acc, 0.f);
    }
    __syncthreads();

    if (t < 32) {
        float a = hid[t] * w1[t] + hid[t + 32] * w1[t + 32];
#pragma unroll
        for (int off = 16; off; off >>= 1) a += __shfl_xor_sync(0xffffffffu, a, off);
        if (t == 0) out[b] = a + b1[0];
    }
}

// ---------------- launch ----------------
extern "C" void kernel_launch(void* const* d_in, const int* in_sizes, int n_in,
                              void* d_out, int out_size) {
    (void)in_sizes; (void)n_in; (void)out_size;
    const int* edge   = (const int*)d_in[1];   // int32 (JAX x64 disabled)
    const int* ptr    = (const int*)d_in[2];   // int32
    const float* emb  = (const float*)d_in[3];
    const float* linw = (const float*)d_in[4];
    const float* attS = (const float*)d_in[5];
    const float* attD = (const float*)d_in[6];
    const float* w0   = (const float*)d_in[7];
    const float* b0   = (const float*)d_in[8];
    const float* w1   = (const float*)d_in[9];
    const float* b1   = (const float*)d_in[10];
    float* out = (float*)d_out;
    const int* esrc = edge;
    const int* edst = edge + EE;

    // CSR build
    k_initcnt<<<(NN + 255) / 256, 256>>>();
    k_count<<<(EE + 255) / 256, 256>>>(edst);
    k_scan<<<1, 1024>>>();
    k_prepfill<<<(NN + 255) / 256, 256>>>();
    k_fill<<<(EE + 255) / 256, 256>>>(esrc, edst);
    k_sortseg<<<(NN + 255) / 256, 256>>>();

    // layer 0 (closed form) -> g_hA
    k_z0<<<1, 128>>>(emb, linw);
    k_h1<<<(NN * DD + 255) / 256, 256>>>(emb);

    int gemmBlocks = (NN + 127) / 128;
    int warpBlocks = (NN * 32 + 255) / 256;

    // layer 1: g_hA -> g_hB
    k_gemm<<<gemmBlocks, 256>>>(1, linw + 1 * DD * DD);
    k_att<<<warpBlocks, 256>>>(attS + 1 * 128, attD + 1 * 128);
    k_agg<<<warpBlocks, 256>>>(1);

    // layer 2: g_hB -> g_hA
    k_gemm<<<gemmBlocks, 256>>>(0, linw + 2 * DD * DD);
    k_att<<<warpBlocks, 256>>>(attS + 2 * 128, attD + 2 * 128);
    k_agg<<<warpBlocks, 256>>>(0);

    // readout
    k_readout<<<BB, 256>>>(ptr, w0, b0, w1, b1, out);
}

// round 3
// speedup vs baseline: 1.2448x; 1.2448x over previous
#include <cuda_runtime.h>

#define NN 50000
#define EE 600000
#define DD 128
#define BB 128

typedef unsigned long long ull;

// ---------------- scratch (device globals: allocation-free) ----------------
__device__ int   g_cnt[NN];          // in-degree incl. self-loop
__device__ int   g_rowoff[NN + 1];   // CSR row offsets (by dst)
__device__ int   g_fill[NN];         // atomic fill cursors
__device__ int   g_csr[EE + NN];     // src indices per dst
__device__ float g_z[NN * DD];
__device__ float g_hA[NN * DD];
__device__ float g_hB[NN * DD];
__device__ float g_as[NN * 4];
__device__ float g_ad[NN * 4];
__device__ float g_z0[DD];

// ---------------- f32x2 packed math helpers ----------------
__device__ __forceinline__ ull pk2(float x, float y) {
    ull r;
    asm("mov.b64 %0, {%1, %2};" : "=l"(r) : "r"(__float_as_uint(x)), "r"(__float_as_uint(y)));
    return r;
}
__device__ __forceinline__ void upk2(ull v, float& x, float& y) {
    unsigned int a, b;
    asm("mov.b64 {%0, %1}, %2;" : "=r"(a), "=r"(b) : "l"(v));
    x = __uint_as_float(a); y = __uint_as_float(b);
}
__device__ __forceinline__ void fma2(ull& c, ull a, ull b) {
    asm("fma.rn.f32x2 %0, %1, %2, %3;" : "=l"(c) : "l"(a), "l"(b), "l"(c));
}

// ---------------- CSR construction ----------------
__global__ void k_initcnt() {
    int i = blockIdx.x * blockDim.x + threadIdx.x;
    if (i < NN) g_cnt[i] = 1;  // self-loop
}

__global__ void k_count(const int* __restrict__ dst) {
    int e = blockIdx.x * blockDim.x + threadIdx.x;
    if (e < EE) atomicAdd(&g_cnt[dst[e]], 1);
}

__global__ void k_scan() {  // exclusive scan of g_cnt -> g_rowoff (single block, 1024 thr)
    __shared__ int wsum[32];
    int t = threadIdx.x, lane = t & 31, wid = t >> 5;
    int carry = 0;
    if (t == 0) g_rowoff[0] = 0;
    for (int base = 0; base < NN; base += 1024) {
        int i = base + t;
        int v = (i < NN) ? g_cnt[i] : 0;
        int x = v;
#pragma unroll
        for (int off = 1; off < 32; off <<= 1) {
            int y = __shfl_up_sync(0xffffffffu, x, off);
            if (lane >= off) x += y;
        }
        if (lane == 31) wsum[wid] = x;
        __syncthreads();
        if (wid == 0) {
            int s = wsum[lane];
#pragma unroll
            for (int off = 1; off < 32; off <<= 1) {
                int y = __shfl_up_sync(0xffffffffu, s, off);
                if (lane >= off) s += y;
            }
            wsum[lane] = s;
        }
        __syncthreads();
        int pref = wid ? wsum[wid - 1] : 0;
        if (i < NN) g_rowoff[i + 1] = carry + pref + x;
        int tot = wsum[31];
        __syncthreads();
        carry += tot;
    }
}

__global__ void k_prepfill() {  // self-loop goes in slot 0 of each segment
    int n = blockIdx.x * blockDim.x + threadIdx.x;
    if (n < NN) {
        int r = g_rowoff[n];
        g_csr[r] = n;
        g_fill[n] = r + 1;
    }
}

__global__ void k_fill(const int* __restrict__ src, const int* __restrict__ dst) {
    int e = blockIdx.x * blockDim.x + threadIdx.x;
    if (e < EE) {
        int d = dst[e];
        int p = atomicAdd(&g_fill[d], 1);
        g_csr[p] = src[e];
    }
}

__global__ void k_sortseg() {  // deterministic order within each dst segment
    int n = blockIdx.x * blockDim.x + threadIdx.x;
    if (n >= NN) return;
    int r0 = g_rowoff[n], r1 = g_rowoff[n + 1];
    for (int i = r0 + 1; i < r1; i++) {
        int v = g_csr[i];
        int j = i - 1;
        while (j >= r0 && g_csr[j] > v) { g_csr[j + 1] = g_csr[j]; j--; }
        g_csr[j + 1] = v;
    }
}

// ---------------- layer 0 closed form ----------------
// h0 rows identical -> alpha uniform -> softmax = 1/deg -> out0 = z0*(1+deg)
__global__ void k_z0(const float* __restrict__ emb, const float* __restrict__ W0) {
    __shared__ float se[DD];
    int t = threadIdx.x;
    se[t] = emb[t];
    __syncthreads();
    float acc = 0.f;
    for (int k = 0; k < DD; k++) acc += se[k] * W0[k * DD + t];
    g_z0[t] = acc;
}

__global__ void k_h1(const float* __restrict__ emb) {
    int idx = blockIdx.x * blockDim.x + threadIdx.x;
    if (idx >= NN * DD) return;
    int n = idx >> 7, d = idx & 127;
    float o = g_z0[d] * (1.0f + (float)g_cnt[n]);
    o = o > 0.f ? o : expm1f(o);   // elu
    g_hA[idx] = o + emb[d];        // residual (h0 = emb row 0)
}

// ---------------- GEMM: z = h @ W  (M=50000, N=K=128), FFMA2 ----------------
// 128 threads: ty(0..7) owns 16 rows (4 groups of 4), tx(0..15) owns 8 cols
// (two float4 groups). Accumulators are packed f32x2 pairs.
__global__ void __launch_bounds__(128) k_gemm(int srcA, const float* __restrict__ W) {
    const float* __restrict__ A = srcA ? g_hA : g_hB;
    __shared__ float As[128][33];   // [m][k], padded: conflict-free scalar access
    __shared__ float Bs[32][128];   // [k][c]
    int tid = threadIdx.x;
    int tx = tid & 15, ty = tid >> 4;
    int row0 = blockIdx.x * 128;

    ull acc[16][4];
#pragma unroll
    for (int r = 0; r < 16; r++)
#pragma unroll
        for (int j = 0; j < 4; j++) acc[r][j] = 0ULL;

    for (int k0 = 0; k0 < 128; k0 += 32) {
        // load A tile 128x32 (coalesced float4 global reads)
#pragma unroll
        for (int i = 0; i < 8; i++) {
            int lin = tid + i * 128;   // 0..1023 float4 units
            int m = lin >> 3, kq = lin & 7;
            int row = row0 + m;
            float4 v = make_float4(0.f, 0.f, 0.f, 0.f);
            if (row < NN) v = *(const float4*)&A[row * 128 + k0 + kq * 4];
            As[m][kq * 4 + 0] = v.x; As[m][kq * 4 + 1] = v.y;
            As[m][kq * 4 + 2] = v.z; As[m][kq * 4 + 3] = v.w;
        }
        // load W tile 32x128 (fully coalesced)
#pragma unroll
        for (int i = 0; i < 8; i++) {
            int lin = tid + i * 128;
            int k = lin >> 5, cq = lin & 31;
            *(float4*)&Bs[k][cq * 4] = *(const float4*)&W[(k0 + k) * 128 + cq * 4];
        }
        __syncthreads();
#pragma unroll
        for (int k = 0; k < 32; k++) {
            float4 b0 = *(const float4*)&Bs[k][tx * 4];
            float4 b1 = *(const float4*)&Bs[k][64 + tx * 4];
            ull pb0 = pk2(b0.x, b0.y), pb1 = pk2(b0.z, b0.w);
            ull pb2 = pk2(b1.x, b1.y), pb3 = pk2(b1.z, b1.w);
#pragma unroll
            for (int r = 0; r < 16; r++) {
                int g = r >> 2, i = r & 3;
                float av = As[g * 32 + ty * 4 + i][k];
                ull pa = pk2(av, av);
                fma2(acc[r][0], pa, pb0);
                fma2(acc[r][1], pa, pb1);
                fma2(acc[r][2], pa, pb2);
                fma2(acc[r][3], pa, pb3);
            }
        }
        __syncthreads();
    }
#pragma unroll
    for (int r = 0; r < 16; r++) {
        int g = r >> 2, i = r & 3;
        int row = row0 + g * 32 + ty * 4 + i;
        if (row < NN) {
            float x0, x1, x2, x3;
            upk2(acc[r][0], x0, x1); upk2(acc[r][1], x2, x3);
            *(float4*)&g_z[row * 128 + tx * 4] = make_float4(x0, x1, x2, x3);
            upk2(acc[r][2], x0, x1); upk2(acc[r][3], x2, x3);
            *(float4*)&g_z[row * 128 + 64 + tx * 4] = make_float4(x0, x1, x2, x3);
        }
    }
}

// ---------------- attention dot products: a_s[n,h], a_d[n,h] ----------------
__global__ void k_att(const float* __restrict__ attS, const float* __restrict__ attD) {
    int warp = (blockIdx.x * blockDim.x + threadIdx.x) >> 5;
    int lane = threadIdx.x & 31;
    if (warp >= NN) return;
    float4 z4 = *(const float4*)&g_z[warp * 128 + lane * 4];
    float4 s4 = *(const float4*)&attS[lane * 4];
    float4 d4 = *(const float4*)&attD[lane * 4];
    float ps = z4.x * s4.x + z4.y * s4.y + z4.z * s4.z + z4.w * s4.w;
    float pd = z4.x * d4.x + z4.y * d4.y + z4.z * d4.z + z4.w * d4.w;
#pragma unroll
    for (int off = 4; off; off >>= 1) {
        ps += __shfl_xor_sync(0xffffffffu, ps, off);
        pd += __shfl_xor_sync(0xffffffffu, pd, off);
    }
    if ((lane & 7) == 0) {
        int h = lane >> 3;
        g_as[warp * 4 + h] = ps;
        g_ad[warp * 4 + h] = pd;
    }
}

// ---------------- aggregation: softmax over in-edges + residual + elu ----------------
__global__ void __launch_bounds__(256) k_agg(int srcA) {
    const float* __restrict__ hin  = srcA ? g_hA : g_hB;
    float* __restrict__       hout = srcA ? g_hB : g_hA;
    int warp = (blockIdx.x * blockDim.x + threadIdx.x) >> 5;
    int lane = threadIdx.x & 31;
    if (warp >= NN) return;
    int n = warp;
    int r0 = g_rowoff[n], r1 = g_rowoff[n + 1];
    float4 ad4 = *(const float4*)&g_ad[n * 4];

    // pass 1: per-head max of leaky_relu(a_s[src]+a_d[n])
    float m0 = -1e30f, m1 = -1e30f, m2 = -1e30f, m3 = -1e30f;
    for (int i = r0 + lane; i < r1; i += 32) {
        int s = g_csr[i];
        float4 as4 = *(const float4*)&g_as[s * 4];
        float t0 = as4.x + ad4.x; t0 = t0 > 0.f ? t0 : 0.2f * t0; m0 = fmaxf(m0, t0);
        float t1 = as4.y + ad4.y; t1 = t1 > 0.f ? t1 : 0.2f * t1; m1 = fmaxf(m1, t1);
        float t2 = as4.z + ad4.z; t2 = t2 > 0.f ? t2 : 0.2f * t2; m2 = fmaxf(m2, t2);
        float t3 = as4.w + ad4.w; t3 = t3 > 0.f ? t3 : 0.2f * t3; m3 = fmaxf(m3, t3);
    }
#pragma unroll
    for (int off = 16; off; off >>= 1) {
        m0 = fmaxf(m0, __shfl_xor_sync(0xffffffffu, m0, off));
        m1 = fmaxf(m1, __shfl_xor_sync(0xffffffffu, m1, off));
        m2 = fmaxf(m2, __shfl_xor_sync(0xffffffffu, m2, off));
        m3 = fmaxf(m3, __shfl_xor_sync(0xffffffffu, m3, off));
    }
    int hh = lane >> 3;  // each lane owns 4 feature dims, all in one head
    float mh  = hh == 0 ? m0 : (hh == 1 ? m1 : (hh == 2 ? m2 : m3));
    float adh = hh == 0 ? ad4.x : (hh == 1 ? ad4.y : (hh == 2 ? ad4.z : ad4.w));

    // pass 2: den + weighted sum + plain sum (edges 2-way unrolled for MLP)
    float den = 0.f;
    float w0 = 0.f, w1 = 0.f, w2 = 0.f, w3 = 0.f;
    float s0 = 0.f, s1 = 0.f, s2 = 0.f, s3 = 0.f;
    for (int c0 = r0; c0 < r1; c0 += 32) {
        int myi = c0 + lane;
        int mysrc = (myi < r1) ? g_csr[myi] : 0;
        int lim = min(32, r1 - c0);
        int j = 0;
        for (; j + 2 <= lim; j += 2) {
            int sa = __shfl_sync(0xffffffffu, mysrc, j);
            int sb = __shfl_sync(0xffffffffu, mysrc, j + 1);
            float ava = g_as[sa * 4 + hh];
            float avb = g_as[sb * 4 + hh];
            float4 za = *(const float4*)&g_z[sa * 128 + lane * 4];
            float4 zb = *(const float4*)&g_z[sb * 128 + lane * 4];
            float ta = ava + adh; ta = ta > 0.f ? ta : 0.2f * ta;
            float tb = avb + adh; tb = tb > 0.f ? tb : 0.2f * tb;
            float exa = __expf(ta - mh);
            float exb = __expf(tb - mh);
            den += exa + exb;
            w0 += exa * za.x + exb * zb.x; s0 += za.x + zb.x;
            w1 += exa * za.y + exb * zb.y; s1 += za.y + zb.y;
            w2 += exa * za.z + exb * zb.z; s2 += za.z + zb.z;
            w3 += exa * za.w + exb * zb.w; s3 += za.w + zb.w;
        }
        for (; j < lim; j++) {
            int s = __shfl_sync(0xffffffffu, mysrc, j);
            float av = g_as[s * 4 + hh];
            float t = av + adh; t = t > 0.f ? t : 0.2f * t;
            float ex = __expf(t - mh);
            den += ex;
            float4 z4 = *(const float4*)&g_z[s * 128 + lane * 4];
            w0 += ex * z4.x; s0 += z4.x;
            w1 += ex * z4.y; s1 += z4.y;
            w2 += ex * z4.z; s2 += z4.z;
            w3 += ex * z4.w; s3 += z4.w;
        }
    }
    float inv = 1.0f / den;
    float4 hv = *(const float4*)&hin[n * 128 + lane * 4];
    float o0 = w0 * inv + s0; o0 = o0 > 0.f ? o0 : expm1f(o0); o0 += hv.x;
    float o1 = w1 * inv + s1; o1 = o1 > 0.f ? o1 : expm1f(o1); o1 += hv.y;
    float o2 = w2 * inv + s2; o2 = o2 > 0.f ? o2 : expm1f(o2); o2 += hv.z;
    float o3 = w3 * inv + s3; o3 = o3 > 0.f ? o3 : expm1f(o3); o3 += hv.w;
    *(float4*)&hout[n * 128 + lane * 4] = make_float4(o0, o1, o2, o3);
}

// ---------------- readout: segment mean (ptr sorted) + MLP ----------------
__device__ __forceinline__ int lbound(const int* p, int n, int v) {
    int lo = 0, hi = n;
    while (lo < hi) {
        int mid = (lo + hi) >> 1;
        if (p[mid] < v) lo = mid + 1; else hi = mid;
    }
    return lo;
}

__global__ void k_readout(const int* __restrict__ ptr,
                          const float* __restrict__ w0, const float* __restrict__ b0,
                          const float* __restrict__ w1, const float* __restrict__ b1,
                          float* __restrict__ out) {
    const float* __restrict__ h = g_hA;  // final features live in g_hA
    int b = blockIdx.x;
    __shared__ int sb[2];
    int t = threadIdx.x;
    if (t == 0) sb[0] = lbound(ptr, NN, b);
    if (t == 1) sb[1] = lbound(ptr, NN, b + 1);
    __syncthreads();
    int lo = sb[0], hi = sb[1];

    __shared__ float red[256];
    int d = t & 127, half = t >> 7;
    float s = 0.f;
    for (int r = lo + half; r < hi; r += 2) s += h[r * 128 + d];
    red[t] = s;
    __syncthreads();

    __shared__ float g[128];
    if (t < 128) {
        float gv = red[t] + red[t + 128];
        int cnt = hi - lo; if (cnt < 1) cnt = 1;
        gv = gv / (float)cnt;
        g[t] = fmaxf(gv, 0.f);
    }
    __syncthreads();

    __shared__ float hid[64];
    if (t < 64) {
        float acc = b0[t];
        for (int k = 0; k < 128; k++) acc += g[k] * w0[k * 64 + t];
        hid[t] = fmaxf(acc, 0.f);
    }
    __syncthreads();

    if (t < 32) {
        float a = hid[t] * w1[t] + hid[t + 32] * w1[t + 32];
#pragma unroll
        for (int off = 16; off; off >>= 1) a += __shfl_xor_sync(0xffffffffu, a, off);
        if (t == 0) out[b] = a + b1[0];
    }
}

// ---------------- launch ----------------
extern "C" void kernel_launch(void* const* d_in, const int* in_sizes, int n_in,
                              void* d_out, int out_size) {
    (void)in_sizes; (void)n_in; (void)out_size;
    const int* edge   = (const int*)d_in[1];   // int32 (JAX x64 disabled)
    const int* ptr    = (const int*)d_in[2];   // int32
    const float* emb  = (const float*)d_in[3];
    const float* linw = (const float*)d_in[4];
    const float* attS = (const float*)d_in[5];
    const float* attD = (const float*)d_in[6];
    const float* w0   = (const float*)d_in[7];
    const float* b0   = (const float*)d_in[8];
    const float* w1   = (const float*)d_in[9];
    const float* b1   = (const float*)d_in[10];
    float* out = (float*)d_out;
    const int* esrc = edge;
    const int* edst = edge + EE;

    static cudaStream_t s_side = nullptr;
    static cudaEvent_t evFork = nullptr, evJoin = nullptr;
    if (!s_side) {
        cudaStreamCreateWithFlags(&s_side, cudaStreamNonBlocking);
        cudaEventCreateWithFlags(&evFork, cudaEventDisableTiming);
        cudaEventCreateWithFlags(&evJoin, cudaEventDisableTiming);
    }

    int gemmBlocks = (NN + 127) / 128;
    int warpBlocks = (NN * 32 + 255) / 256;

    // main stream: degree count + layer 0 + gemm1/att1
    k_z0<<<1, 128>>>(emb, linw);
    k_initcnt<<<(NN + 255) / 256, 256>>>();
    k_count<<<(EE + 255) / 256, 256>>>(edst);

    // fork: CSR build (scan/prepfill/fill/sort) on side stream, overlapped
    cudaEventRecord(evFork, 0);
    cudaStreamWaitEvent(s_side, evFork, 0);
    k_scan<<<1, 1024, 0, s_side>>>();
    k_prepfill<<<(NN + 255) / 256, 256, 0, s_side>>>();
    k_fill<<<(EE + 255) / 256, 256, 0, s_side>>>(esrc, edst);
    k_sortseg<<<(NN + 255) / 256, 256, 0, s_side>>>();
    cudaEventRecord(evJoin, s_side);

    // main continues: layer 0 closed form -> g_hA, then gemm1/att1
    k_h1<<<(NN * DD + 255) / 256, 256>>>(emb);
    k_gemm<<<gemmBlocks, 128>>>(1, linw + 1 * DD * DD);
    k_att<<<warpBlocks, 256>>>(attS + 1 * 128, attD + 1 * 128);

    // join: aggregation needs the CSR
    cudaStreamWaitEvent(0, evJoin, 0);
    k_agg<<<warpBlocks, 256>>>(1);

    // layer 2: g_hB -> g_hA
    k_gemm<<<gemmBlocks, 128>>>(0, linw + 2 * DD * DD);
    k_att<<<warpBlocks, 256>>>(attS + 2 * 128, attD + 2 * 128);
    k_agg<<<warpBlocks, 256>>>(0);

    // readout
    k_readout<<<BB, 256>>>(ptr, w0, b0, w1, b1, out);
}